// round 14
// baseline (speedup 1.0000x reference)
#include <cuda_runtime.h>

// Rotation_agg: out[n, :] = mean_l ( cmul(feat[n,l,:], finals[l,:]) ), finals[3]=identity.
// Converged HBM-bound stream (1.28 GB minimal traffic, ~7.15 TB/s = 90% of spec across
// 8 structural variants). R10: identical access pattern, block size 256 -> 512 to halve
// per-block prologue (coeff compute + barrier) and block-boundary count.

#define ROT_EPS 1e-12f

__global__ __launch_bounds__(512) void rotation_agg_kernel(
    const float* __restrict__ feat,
    const float* __restrict__ r_vec,
    float* __restrict__ out,
    int total32)   // N*16 work items
{
    __shared__ float2 sf[3][32];   // finals for l=0,1,2 per complex index k

    const int tid = threadIdx.x;
    if (tid < 32) {
        const int k = tid;
        float2 rn[3];
#pragma unroll
        for (int e = 0; e < 3; e++) {
            float x = r_vec[e * 64 + k * 2 + 0];
            float y = r_vec[e * 64 + k * 2 + 1];
            float nrm = sqrtf(x * x + y * y);
            float inv = 1.0f / fmaxf(nrm, ROT_EPS);
            rn[e] = make_float2(x * inv, y * inv);
        }
        float2 f2 = make_float2(rn[2].x, -rn[2].y);               // conj(rn2)
        float2 c1 = make_float2(rn[1].x, -rn[1].y);               // conj(rn1)
        float2 f1 = make_float2(f2.x * c1.x - f2.y * c1.y,
                                f2.x * c1.y + f2.y * c1.x);       // f2 * conj(rn1)
        float2 f0 = make_float2(f1.x * rn[0].x - f1.y * rn[0].y,
                                f1.x * rn[0].y + f1.y * rn[0].x); // f1 * rn0
        sf[0][k] = f0;
        sf[1][k] = f1;
        sf[2][k] = f2;
    }
    __syncthreads();

    const int t = blockIdx.x * 512 + tid;
    if (t >= total32) return;

    const int n = t >> 4;
    const int c = t & 15;                        // float4 column -> complex pairs 2c, 2c+1

    const float4* in4 = (const float4*)feat + (long long)n * 64 + c;  // 64 float4 per n

    // Batch all 4 layer loads up front (MLP=4); evict-first streaming policy.
    float4 v0 = __ldcs(in4 + 0);
    float4 v1 = __ldcs(in4 + 16);
    float4 v2 = __ldcs(in4 + 32);
    float4 v3 = __ldcs(in4 + 48);

    const float2 f00 = sf[0][2 * c], f01 = sf[0][2 * c + 1];
    const float2 f10 = sf[1][2 * c], f11 = sf[1][2 * c + 1];
    const float2 f20 = sf[2][2 * c], f21 = sf[2][2 * c + 1];

    float4 acc;
    acc.x = v3.x + (v0.x * f00.x - v0.y * f00.y)
                 + (v1.x * f10.x - v1.y * f10.y)
                 + (v2.x * f20.x - v2.y * f20.y);
    acc.y = v3.y + (v0.x * f00.y + v0.y * f00.x)
                 + (v1.x * f10.y + v1.y * f10.x)
                 + (v2.x * f20.y + v2.y * f20.x);
    acc.z = v3.z + (v0.z * f01.x - v0.w * f01.y)
                 + (v1.z * f11.x - v1.w * f11.y)
                 + (v2.z * f21.x - v2.w * f21.y);
    acc.w = v3.w + (v0.z * f01.y + v0.w * f01.x)
                 + (v1.z * f11.y + v1.w * f11.x)
                 + (v2.z * f21.y + v2.w * f21.x);

    acc.x *= 0.25f; acc.y *= 0.25f; acc.z *= 0.25f; acc.w *= 0.25f;

    __stcs((float4*)out + (long long)n * 16 + c, acc);
}

extern "C" void kernel_launch(void* const* d_in, const int* in_sizes, int n_in,
                              void* d_out, int out_size)
{
    const float* feat  = (const float*)d_in[0];   // (N, 4, 64) fp32
    const float* r_vec = (const float*)d_in[1];   // (4, 32, 2) fp32
    float* out = (float*)d_out;                   // (N, 64) fp32

    const int N = in_sizes[0] / 256;              // 4*64 floats per row
    const int total = N * 16;                     // float4 work items
    const int threads = 512;
    const int blocks = (total + threads - 1) / threads;

    rotation_agg_kernel<<<blocks, threads>>>(feat, r_vec, out, total);
}